// round 12
// baseline (speedup 1.0000x reference)
#include <cuda_runtime.h>
#include <cstdint>
#include <cstddef>

#define T_LEN 2048
#define I_DIM 1739
#define H_DIM 256
#define G3    768          // 3*H
#define NCTA  8            // cluster size for the recurrence
#define THREADS_GRU 512    // 16 warps; each warp owns TWO adjacent hidden units

// ---------------- scratch (module-static device globals; no runtime alloc) ----
__device__ float g_xproj_enc[T_LEN * G3];
__device__ float g_xproj_dec[T_LEN * G3];
__device__ float g_hs[T_LEN * H_DIM];
__device__ float g_henc[H_DIM];

// ---------------- fp32 tiled GEMM:  C[M,N] = A[M,K] @ B[N,K]^T + bias[N] -----
// 128x128 tile, 256 threads, 8x8 per thread. Warp tile 32x64.
#define BM 128
#define BN 128
#define BK 16

__global__ void __launch_bounds__(256) gemm_bias_kernel(
    const float* __restrict__ A, const float* __restrict__ B,
    const float* __restrict__ bias, float* __restrict__ C,
    int M, int N, int K)
{
    __shared__ float As[BK][BM + 4];
    __shared__ float Bs[BK][BN + 4];

    const int tid  = threadIdx.x;
    const int lane = tid & 31;
    const int w    = tid >> 5;            // 0..7
    const int wr   = w >> 1;              // 0..3 : warp row (32 rows each)
    const int wc   = w & 1;               // 0..1 : warp col (64 cols each)
    const int lr   = lane >> 3;           // 0..3
    const int lcn  = lane & 7;            // 0..7

    const int row0 = blockIdx.y * BM;
    const int col0 = blockIdx.x * BN;
    const int r0   = wr * 32 + lr * 4;    // within-tile row frag base
    const int c0   = wc * 64 + lcn * 4;   // within-tile col frag base

    // tile loaders: 128 rows x 16 k per tile; thread loads 8 contiguous k of 1 row
    const int lrow = tid >> 1;            // 0..127
    const int lk0  = (tid & 1) * 8;       // 0 or 8

    const float* Arow = A + (size_t)(row0 + lrow) * K;   // M multiple of 128
    const int    brow = col0 + lrow;
    const float* Brow = B + (size_t)brow * K;
    const bool   bvalid = brow < N;

    float acc[8][8] = {};

    for (int k0 = 0; k0 < K; k0 += BK) {
        #pragma unroll
        for (int i = 0; i < 8; i++) {
            const int gc = k0 + lk0 + i;
            As[lk0 + i][lrow] = (gc < K) ? Arow[gc] : 0.f;
            Bs[lk0 + i][lrow] = (bvalid && gc < K) ? Brow[gc] : 0.f;
        }
        __syncthreads();

        #pragma unroll
        for (int k = 0; k < BK; k++) {
            const float4 a0 = *(const float4*)&As[k][r0];
            const float4 a1 = *(const float4*)&As[k][r0 + 16];
            const float4 b0 = *(const float4*)&Bs[k][c0];
            const float4 b1 = *(const float4*)&Bs[k][c0 + 32];
            const float av[8] = {a0.x, a0.y, a0.z, a0.w, a1.x, a1.y, a1.z, a1.w};
            const float bv[8] = {b0.x, b0.y, b0.z, b0.w, b1.x, b1.y, b1.z, b1.w};
            #pragma unroll
            for (int i = 0; i < 8; i++)
                #pragma unroll
                for (int j = 0; j < 8; j++)
                    acc[i][j] += av[i] * bv[j];
        }
        __syncthreads();
    }

    #pragma unroll
    for (int i = 0; i < 8; i++) {
        const int r = row0 + r0 + ((i < 4) ? i : (16 + i - 4));
        #pragma unroll
        for (int j = 0; j < 8; j++) {
            const int c = col0 + c0 + ((j < 4) ? j : (32 + j - 4));
            if (c < N) C[(size_t)r * N + c] = acc[i][j] + bias[c];
        }
    }
}

// ---------------- GRU recurrence: 8-CTA cluster, packed-b64 st.async exchange --
//
// 8 CTAs x 512 threads (16 warps). Warp w of CTA c owns units j0 = c*32 + 2w
// and j0+1 (6 W_hh rows in registers as f32x2: 24 FFMA2/step). Per step:
// try_wait on this parity's mbarrier (1024B = 128 producer warps x 8B via
// st.async.b64), LDS h slice, 24 FFMA2, 6x shfl butterfly, both units' gate
// math in all lanes (warp-uniform); lanes 0..7 each send ONE packed b64
// (hnew0, hnew1) to cluster CTA d=lane (8B complete_tx). 128 arrivals per
// dest mbar instead of 256; 4 warps/SMSP instead of 8 halves issue pressure.
// No barrier.cluster, no __syncthreads in the loop.
//
// 2-buffer safety is causal: a gen g+2 store can only be issued by a producer
// that consumed gen g+1, which required THIS CTA's gen g+1 store, which was
// issued only after this CTA passed its gen-g wait (barrier already flipped).

__device__ __forceinline__ uint32_t smem_u32(const void* p) {
    uint32_t a;
    asm("{ .reg .u64 t; cvta.to.shared.u64 t, %1; cvt.u32.u64 %0, t; }"
        : "=r"(a) : "l"(p));
    return a;
}

__device__ __forceinline__ float sigmoid_fast(float x) {
    return __fdividef(1.f, 1.f + __expf(-x));
}
__device__ __forceinline__ float tanh_fast(float x) {
    return 1.f - __fdividef(2.f, __expf(2.f * x) + 1.f);
}

__device__ __forceinline__ unsigned long long pack2(float lo, float hi) {
    unsigned long long r;
    asm("mov.b64 %0, {%1, %2};" : "=l"(r) : "f"(lo), "f"(hi));
    return r;
}
__device__ __forceinline__ unsigned long long mul2(unsigned long long a, unsigned long long b) {
    unsigned long long d;
    asm("mul.rn.f32x2 %0, %1, %2;" : "=l"(d) : "l"(a), "l"(b));
    return d;
}
__device__ __forceinline__ unsigned long long fma2(unsigned long long a, unsigned long long b,
                                                   unsigned long long c) {
    unsigned long long d;
    asm("fma.rn.f32x2 %0, %1, %2, %3;" : "=l"(d) : "l"(a), "l"(b), "l"(c));
    return d;
}
__device__ __forceinline__ float hsum2(unsigned long long v) {
    float lo, hi;
    asm("mov.b64 {%0, %1}, %2;" : "=f"(lo), "=f"(hi) : "l"(v));
    return lo + hi;
}

__device__ __forceinline__ void mbar_wait_acq_cluster(uint32_t mb, uint32_t parity) {
    asm volatile(
        "{\n\t.reg .pred P;\n\t"
        "LW_%=:\n\t"
        "mbarrier.try_wait.parity.acquire.cluster.shared::cta.b64 P, [%0], %1, 0x989680;\n\t"
        "@P bra LD_%=;\n\t"
        "bra LW_%=;\n\t"
        "LD_%=:\n\t}"
        :: "r"(mb), "r"(parity) : "memory");
}

__global__ void __cluster_dims__(NCTA, 1, 1) __launch_bounds__(THREADS_GRU, 1)
gru_kernel(const float* __restrict__ xproj, const float* __restrict__ Whh,
           const float* __restrict__ bhh,   const float* __restrict__ h0,
           float* __restrict__ hs_out,      float* __restrict__ hT_out)
{
    __shared__ __align__(16) float h_buf[2][H_DIM];
    __shared__ __align__(8)  unsigned long long mbar[2];

    const int tid  = threadIdx.x;
    const int wid  = tid >> 5;
    const int lane = tid & 31;
    uint32_t rank;
    asm("mov.u32 %0, %%cluster_ctarank;" : "=r"(rank));
    const int j0 = (int)rank * 32 + wid * 2;     // first of the two owned units

    // Register-resident weights (f32x2): rows {j0,j0+1} x gates {r,z,n},
    // cols [8*lane, 8*lane+8).  wp[u*3+g]
    unsigned long long wp[6][4];
    {
        const int rows[6] = {j0, j0 + 256, j0 + 512, j0 + 1, j0 + 257, j0 + 513};
        #pragma unroll
        for (int rI = 0; rI < 6; rI++) {
            const float4* pr = (const float4*)(Whh + (size_t)rows[rI] * H_DIM + lane * 8);
            float4 a = pr[0], b = pr[1];
            wp[rI][0] = pack2(a.x, a.y); wp[rI][1] = pack2(a.z, a.w);
            wp[rI][2] = pack2(b.x, b.y); wp[rI][3] = pack2(b.z, b.w);
        }
    }
    const float bhr0 = bhh[j0],     bhz0 = bhh[j0 + 256], bhn0 = bhh[j0 + 512];
    const float bhr1 = bhh[j0 + 1], bhz1 = bhh[j0 + 257], bhn1 = bhh[j0 + 513];

    const uint32_t hbase_loc = smem_u32(&h_buf[0][0]);
    const uint32_t mbar_loc  = smem_u32(&mbar[0]);

    // init: mbarriers (count=1) + h_0 local copy
    if (tid == 0) {
        asm volatile("mbarrier.init.shared.b64 [%0], 1;" :: "r"(mbar_loc)     : "memory");
        asm volatile("mbarrier.init.shared.b64 [%0], 1;" :: "r"(mbar_loc + 8) : "memory");
    }
    if (tid < H_DIM) h_buf[0][tid] = h0 ? h0[tid] : 0.f;
    __syncthreads();
    // pre-post expectations for the first fill of each buffer (h_1 -> buf1, h_2 -> buf0)
    if (tid == 0) {
        asm volatile("mbarrier.arrive.expect_tx.shared::cta.b64 _, [%0], 1024;" :: "r"(mbar_loc)     : "memory");
        asm volatile("mbarrier.arrive.expect_tx.shared::cta.b64 _, [%0], 1024;" :: "r"(mbar_loc + 8) : "memory");
    }
    float hold0 = h_buf[0][j0], hold1 = h_buf[0][j0 + 1];   // register-carried
    // one-time cluster sync: peers' mbarriers valid before any st.async flies
    asm volatile("barrier.cluster.arrive.aligned;" ::: "memory");
    asm volatile("barrier.cluster.wait.aligned;"   ::: "memory");

    // per-destination remote addresses (lanes 0..7), computed once
    uint32_t ra_h = 0, ra_m = 0;
    if (lane < NCTA) {
        asm("mapa.shared::cluster.u32 %0, %1, %2;" : "=r"(ra_h) : "r"(hbase_loc), "r"(lane));
        asm("mapa.shared::cluster.u32 %0, %1, %2;" : "=r"(ra_m) : "r"(mbar_loc),  "r"(lane));
    }

    int ph0 = 0, ph1 = 0;

    for (int t = 0; t < T_LEN; t++) {
        const int p = t & 1;
        const int q = 1 - p;

        // prefetch xproj pairs (uniform per warp) before the wait: 3x LDG.64
        const float* row = xproj + (size_t)t * G3;
        const float2 xrp = *(const float2*)(row + j0);
        const float2 xzp = *(const float2*)(row + j0 + 256);
        const float2 xnp = *(const float2*)(row + j0 + 512);

        if (t > 0) {
            const uint32_t mb = mbar_loc + (uint32_t)p * 8;
            mbar_wait_acq_cluster(mb, (uint32_t)(p ? ph1 : ph0));
            if (p) ph1 ^= 1; else ph0 ^= 1;
            // repost this buffer's expectation for its next fill (gen t+2)
            if (tid == 17)
                asm volatile("mbarrier.arrive.expect_tx.shared::cta.b64 _, [%0], 1024;"
                             :: "r"(mb) : "memory");
        }

        // matvec partials over this lane's 8 h values, packed f32x2 (24 FFMA2)
        const float4* hb = (const float4*)&h_buf[p][lane * 8];
        const float4 hv0 = hb[0], hv1 = hb[1];
        unsigned long long hp[4];
        hp[0] = pack2(hv0.x, hv0.y); hp[1] = pack2(hv0.z, hv0.w);
        hp[2] = pack2(hv1.x, hv1.y); hp[3] = pack2(hv1.z, hv1.w);

        unsigned long long ac[6];
        #pragma unroll
        for (int rI = 0; rI < 6; rI++) ac[rI] = mul2(wp[rI][0], hp[0]);
        #pragma unroll
        for (int k = 1; k < 4; k++)
            #pragma unroll
            for (int rI = 0; rI < 6; rI++) ac[rI] = fma2(wp[rI][k], hp[k], ac[rI]);

        float a[6];
        #pragma unroll
        for (int rI = 0; rI < 6; rI++) a[rI] = hsum2(ac[rI]);

        // 6 independent 5-round butterflies (chains overlap)
        #pragma unroll
        for (int off = 16; off > 0; off >>= 1) {
            #pragma unroll
            for (int rI = 0; rI < 6; rI++)
                a[rI] += __shfl_xor_sync(0xffffffffu, a[rI], off);
        }

        // gate combine for both units in all lanes (warp-uniform inputs)
        const float r0 = sigmoid_fast(xrp.x + a[0] + bhr0);
        const float z0 = sigmoid_fast(xzp.x + a[1] + bhz0);
        const float n0 = tanh_fast(xnp.x + r0 * (a[2] + bhn0));
        const float hnew0 = n0 + z0 * (hold0 - n0);
        const float r1 = sigmoid_fast(xrp.y + a[3] + bhr1);
        const float z1 = sigmoid_fast(xzp.y + a[4] + bhz1);
        const float n1 = tanh_fast(xnp.y + r1 * (a[5] + bhn1));
        const float hnew1 = n1 + z1 * (hold1 - n1);
        hold0 = hnew0; hold1 = hnew1;

        if (t < T_LEN - 1) {
            // lanes 0..7: ONE packed b64 to buffer q of cluster CTA d=lane,
            // completing 8B of tx on that CTA's mbar[q]
            if (lane < NCTA) {
                const uint32_t daddr = ra_h + (uint32_t)((q * H_DIM + j0) << 2);
                const uint32_t dmbar = ra_m + (uint32_t)(q * 8);
                asm volatile(
                    "st.async.shared::cluster.mbarrier::complete_tx::bytes.b64 [%0], %1, [%2];"
                    :: "r"(daddr), "l"(pack2(hnew0, hnew1)), "r"(dmbar) : "memory");
            }
        }
        if (lane == 8) {
            if (hs_out) *(float2*)(hs_out + (size_t)t * H_DIM + j0) = make_float2(hnew0, hnew1);
            if (t == T_LEN - 1 && hT_out) *(float2*)(hT_out + j0) = make_float2(hnew0, hnew1);
        }
    }

    // no st.async issued for the final step -> no in-flight traffic; sync & exit
    asm volatile("barrier.cluster.arrive.aligned;" ::: "memory");
    asm volatile("barrier.cluster.wait.aligned;"   ::: "memory");
}

// ---------------- launch --------------------------------------------------------
extern "C" void kernel_launch(void* const* d_in, const int* in_sizes, int n_in,
                              void* d_out, int out_size)
{
    const float* x      = (const float*)d_in[0];   // [1, T, I]
    const float* W_ih_e = (const float*)d_in[2];   // [768, 1739]
    const float* W_hh_e = (const float*)d_in[3];   // [768, 256]
    const float* b_ih_e = (const float*)d_in[4];   // [768]
    const float* b_hh_e = (const float*)d_in[5];   // [768]
    const float* W_ih_d = (const float*)d_in[6];
    const float* W_hh_d = (const float*)d_in[7];
    const float* b_ih_d = (const float*)d_in[8];
    const float* b_hh_d = (const float*)d_in[9];
    const float* W_out  = (const float*)d_in[10];  // [1739, 256]
    const float* b_out  = (const float*)d_in[11];  // [1739]
    float* out = (float*)d_out;                    // [2048, 1, 1739]

    float *xpe, *xpd, *hs, *henc;
    cudaGetSymbolAddress((void**)&xpe,  g_xproj_enc);
    cudaGetSymbolAddress((void**)&xpd,  g_xproj_dec);
    cudaGetSymbolAddress((void**)&hs,   g_hs);
    cudaGetSymbolAddress((void**)&henc, g_henc);

    const dim3 blk(256);
    // x-projections (independent)
    gemm_bias_kernel<<<dim3(G3 / BN, T_LEN / BM), blk>>>(x, W_ih_e, b_ih_e, xpe,
                                                         T_LEN, G3, I_DIM);
    gemm_bias_kernel<<<dim3(G3 / BN, T_LEN / BM), blk>>>(x, W_ih_d, b_ih_d, xpd,
                                                         T_LEN, G3, I_DIM);
    // encoder recurrence -> h_enc
    gru_kernel<<<NCTA, THREADS_GRU>>>(xpe, W_hh_e, b_hh_e, nullptr, nullptr, henc);
    // decoder recurrence (h0 = h_enc) -> hs
    gru_kernel<<<NCTA, THREADS_GRU>>>(xpd, W_hh_d, b_hh_d, henc, hs, nullptr);
    // output projection
    gemm_bias_kernel<<<dim3((I_DIM + BN - 1) / BN, T_LEN / BM), blk>>>(
        hs, W_out, b_out, out, T_LEN, I_DIM, H_DIM);
}

// round 17
// speedup vs baseline: 1.1061x; 1.1061x over previous
#include <cuda_runtime.h>
#include <cstdint>
#include <cstddef>

#define T_LEN 2048
#define I_DIM 1739
#define H_DIM 256
#define G3    768          // 3*H
#define NCTA  8            // cluster size for the recurrence
#define NMBAR 4            // mbarriers per parity (accounting parallelism)

// ---------------- scratch (module-static device globals; no runtime alloc) ----
__device__ float g_xproj_enc[T_LEN * G3];
__device__ float g_xproj_dec[T_LEN * G3];
__device__ float g_hs[T_LEN * H_DIM];
__device__ float g_henc[H_DIM];

// ---------------- fp32 tiled GEMM:  C[M,N] = A[M,K] @ B[N,K]^T + bias[N] -----
// 128x128 tile, 256 threads, 8x8 per thread. Warp tile 32x64.
#define BM 128
#define BN 128
#define BK 16

__global__ void __launch_bounds__(256) gemm_bias_kernel(
    const float* __restrict__ A, const float* __restrict__ B,
    const float* __restrict__ bias, float* __restrict__ C,
    int M, int N, int K)
{
    __shared__ float As[BK][BM + 4];
    __shared__ float Bs[BK][BN + 4];

    const int tid  = threadIdx.x;
    const int lane = tid & 31;
    const int w    = tid >> 5;            // 0..7
    const int wr   = w >> 1;              // 0..3 : warp row (32 rows each)
    const int wc   = w & 1;               // 0..1 : warp col (64 cols each)
    const int lr   = lane >> 3;           // 0..3
    const int lcn  = lane & 7;            // 0..7

    const int row0 = blockIdx.y * BM;
    const int col0 = blockIdx.x * BN;
    const int r0   = wr * 32 + lr * 4;    // within-tile row frag base
    const int c0   = wc * 64 + lcn * 4;   // within-tile col frag base

    // tile loaders: 128 rows x 16 k per tile; thread loads 8 contiguous k of 1 row
    const int lrow = tid >> 1;            // 0..127
    const int lk0  = (tid & 1) * 8;       // 0 or 8

    const float* Arow = A + (size_t)(row0 + lrow) * K;   // M multiple of 128
    const int    brow = col0 + lrow;
    const float* Brow = B + (size_t)brow * K;
    const bool   bvalid = brow < N;

    float acc[8][8] = {};

    for (int k0 = 0; k0 < K; k0 += BK) {
        #pragma unroll
        for (int i = 0; i < 8; i++) {
            const int gc = k0 + lk0 + i;
            As[lk0 + i][lrow] = (gc < K) ? Arow[gc] : 0.f;
            Bs[lk0 + i][lrow] = (bvalid && gc < K) ? Brow[gc] : 0.f;
        }
        __syncthreads();

        #pragma unroll
        for (int k = 0; k < BK; k++) {
            const float4 a0 = *(const float4*)&As[k][r0];
            const float4 a1 = *(const float4*)&As[k][r0 + 16];
            const float4 b0 = *(const float4*)&Bs[k][c0];
            const float4 b1 = *(const float4*)&Bs[k][c0 + 32];
            const float av[8] = {a0.x, a0.y, a0.z, a0.w, a1.x, a1.y, a1.z, a1.w};
            const float bv[8] = {b0.x, b0.y, b0.z, b0.w, b1.x, b1.y, b1.z, b1.w};
            #pragma unroll
            for (int i = 0; i < 8; i++)
                #pragma unroll
                for (int j = 0; j < 8; j++)
                    acc[i][j] += av[i] * bv[j];
        }
        __syncthreads();
    }

    #pragma unroll
    for (int i = 0; i < 8; i++) {
        const int r = row0 + r0 + ((i < 4) ? i : (16 + i - 4));
        #pragma unroll
        for (int j = 0; j < 8; j++) {
            const int c = col0 + c0 + ((j < 4) ? j : (32 + j - 4));
            if (c < N) C[(size_t)r * N + c] = acc[i][j] + bias[c];
        }
    }
}

// ---------------- GRU recurrence: 8-CTA cluster, 4-way-split mbarrier sync ----
//
// Round-8 structure (best known): 8 CTAs x 1024 threads, warp w of CTA c owns
// hidden unit j = c*32 + w (rows j, j+256, j+512 register-resident), lanes 0..7
// st.async h_new[j] (4B) to all 8 CTAs. NEW: each parity's arrival accounting
// is split over 4 mbarriers by SOURCE CTA pair (mbar m <- CTAs {2m, 2m+1},
// expect_tx 256B each). Different smem addresses -> parallel accounting units,
// cutting the 256-arrival serialization tail ~4x. Consumer waits all 4 (first
// wait sleeps; the other 3 are fast-path).
//
// 2-buffer safety is causal, per-mbar: a gen g+2 store can only be issued by a
// producer that consumed gen g+1, which required THIS CTA's gen g+1 store,
// which was issued only after this CTA passed its gen-g wait on every mbar.

__device__ __forceinline__ uint32_t smem_u32(const void* p) {
    uint32_t a;
    asm("{ .reg .u64 t; cvta.to.shared.u64 t, %1; cvt.u32.u64 %0, t; }"
        : "=r"(a) : "l"(p));
    return a;
}

__device__ __forceinline__ float sigmoid_fast(float x) {
    return __fdividef(1.f, 1.f + __expf(-x));
}
__device__ __forceinline__ float tanh_fast(float x) {
    return 1.f - __fdividef(2.f, __expf(2.f * x) + 1.f);
}

__device__ __forceinline__ void mbar_wait_acq_cluster(uint32_t mb, uint32_t parity) {
    asm volatile(
        "{\n\t.reg .pred P;\n\t"
        "LW_%=:\n\t"
        "mbarrier.try_wait.parity.acquire.cluster.shared::cta.b64 P, [%0], %1, 0x989680;\n\t"
        "@P bra LD_%=;\n\t"
        "bra LW_%=;\n\t"
        "LD_%=:\n\t}"
        :: "r"(mb), "r"(parity) : "memory");
}

__global__ void __cluster_dims__(NCTA, 1, 1) __launch_bounds__(1024, 1)
gru_kernel(const float* __restrict__ xproj, const float* __restrict__ Whh,
           const float* __restrict__ bhh,   const float* __restrict__ h0,
           float* __restrict__ hs_out,      float* __restrict__ hT_out)
{
    __shared__ __align__(16) float h_buf[2][H_DIM];
    __shared__ __align__(8)  unsigned long long mbar[2][NMBAR];

    const int tid  = threadIdx.x;
    const int wid  = tid >> 5;
    const int lane = tid & 31;
    uint32_t rank;
    asm("mov.u32 %0, %%cluster_ctarank;" : "=r"(rank));
    const int j = (int)rank * 32 + wid;          // hidden unit owned by this warp
    const int src_mbar = (int)(rank >> 1);       // which mbar this CTA's sends hit

    // Register-resident weights: rows j (r), j+256 (z), j+512 (n), cols [8*lane, 8*lane+8)
    float w0[8], w1[8], w2[8];
    {
        const float4* p0 = (const float4*)(Whh + (size_t)j * H_DIM + lane * 8);
        const float4* p1 = (const float4*)(Whh + (size_t)(j + 256) * H_DIM + lane * 8);
        const float4* p2 = (const float4*)(Whh + (size_t)(j + 512) * H_DIM + lane * 8);
        float4 a = p0[0], b = p0[1];
        w0[0]=a.x; w0[1]=a.y; w0[2]=a.z; w0[3]=a.w; w0[4]=b.x; w0[5]=b.y; w0[6]=b.z; w0[7]=b.w;
        a = p1[0]; b = p1[1];
        w1[0]=a.x; w1[1]=a.y; w1[2]=a.z; w1[3]=a.w; w1[4]=b.x; w1[5]=b.y; w1[6]=b.z; w1[7]=b.w;
        a = p2[0]; b = p2[1];
        w2[0]=a.x; w2[1]=a.y; w2[2]=a.z; w2[3]=a.w; w2[4]=b.x; w2[5]=b.y; w2[6]=b.z; w2[7]=b.w;
    }
    const float bhr = bhh[j], bhz = bhh[j + 256], bhn = bhh[j + 512];

    const uint32_t hbase_loc = smem_u32(&h_buf[0][0]);
    const uint32_t mbar_loc  = smem_u32(&mbar[0][0]);

    // init: 8 mbarriers (count=1) + h_0 local copy
    if (tid == 0) {
        #pragma unroll
        for (int m = 0; m < 2 * NMBAR; m++)
            asm volatile("mbarrier.init.shared.b64 [%0], 1;"
                         :: "r"(mbar_loc + m * 8) : "memory");
    }
    if (tid < H_DIM) h_buf[0][tid] = h0 ? h0[tid] : 0.f;
    __syncthreads();
    // pre-post expectations for the first fill of each buffer (256B per mbar)
    if (tid == 0) {
        #pragma unroll
        for (int m = 0; m < 2 * NMBAR; m++)
            asm volatile("mbarrier.arrive.expect_tx.shared::cta.b64 _, [%0], 256;"
                         :: "r"(mbar_loc + m * 8) : "memory");
    }
    float hold = h_buf[0][j];        // register-carried h_old[j] from here on
    // one-time cluster sync: peers' mbarriers valid before any st.async flies
    asm volatile("barrier.cluster.arrive.aligned;" ::: "memory");
    asm volatile("barrier.cluster.wait.aligned;"   ::: "memory");

    // per-destination remote addresses (lanes 0..7), computed once
    uint32_t ra_h = 0, ra_m = 0;
    if (lane < NCTA) {
        asm("mapa.shared::cluster.u32 %0, %1, %2;" : "=r"(ra_h) : "r"(hbase_loc), "r"(lane));
        asm("mapa.shared::cluster.u32 %0, %1, %2;" : "=r"(ra_m) : "r"(mbar_loc),  "r"(lane));
    }

    int ph0 = 0, ph1 = 0;

    for (int t = 0; t < T_LEN; t++) {
        const int p = t & 1;
        const int q = 1 - p;

        // prefetch xproj row (uniform per warp; independent of h) before the wait
        const float* row = xproj + (size_t)t * G3;
        const float xr = row[j], xz = row[j + 256], xn = row[j + 512];

        if (t > 0) {
            const uint32_t ph = (uint32_t)(p ? ph1 : ph0);
            // wait all 4 mbars of this parity (first sleeps; rest fast-path)
            #pragma unroll
            for (int m = 0; m < NMBAR; m++)
                mbar_wait_acq_cluster(mbar_loc + (uint32_t)(p * NMBAR + m) * 8, ph);
            if (p) ph1 ^= 1; else ph0 ^= 1;
            // repost this parity's expectations for its next fill (gen t+2):
            // tids 9..12 (warp 0) each repost one mbar
            if (tid >= 9 && tid < 9 + NMBAR)
                asm volatile("mbarrier.arrive.expect_tx.shared::cta.b64 _, [%0], 256;"
                             :: "r"(mbar_loc + (uint32_t)(p * NMBAR + (tid - 9)) * 8)
                             : "memory");
        }

        // matvec partials: 24 FMAs over this lane's 8 h values
        const float4* hb = (const float4*)&h_buf[p][lane * 8];
        const float4 hv0 = hb[0], hv1 = hb[1];
        const float hv[8] = {hv0.x, hv0.y, hv0.z, hv0.w, hv1.x, hv1.y, hv1.z, hv1.w};
        float a0 = 0.f, a1 = 0.f, a2 = 0.f;
        #pragma unroll
        for (int k = 0; k < 8; k++) {
            a0 += w0[k] * hv[k];
            a1 += w1[k] * hv[k];
            a2 += w2[k] * hv[k];
        }
        // 3 independent 5-round butterflies (chains overlap)
        #pragma unroll
        for (int off = 16; off > 0; off >>= 1) {
            a0 += __shfl_xor_sync(0xffffffffu, a0, off);
            a1 += __shfl_xor_sync(0xffffffffu, a1, off);
            a2 += __shfl_xor_sync(0xffffffffu, a2, off);
        }

        // gate combine in all lanes (warp-uniform inputs)
        const float r    = sigmoid_fast(xr + a0 + bhr);
        const float z    = sigmoid_fast(xz + a1 + bhz);
        const float n    = tanh_fast(xn + r * (a2 + bhn));
        const float hnew = n + z * (hold - n);     // (1-z)*n + z*h
        hold = hnew;

        if (t < T_LEN - 1) {
            // lanes 0..7: deliver h_new[j] to buffer q of cluster CTA d=lane,
            // completing 4B of tx on that CTA's mbar[q][rank>>1]
            if (lane < NCTA) {
                const uint32_t daddr = ra_h + (uint32_t)((q * H_DIM + j) << 2);
                const uint32_t dmbar = ra_m + (uint32_t)((q * NMBAR + src_mbar) * 8);
                asm volatile(
                    "st.async.shared::cluster.mbarrier::complete_tx::bytes.b32 [%0], %1, [%2];"
                    :: "r"(daddr), "r"(__float_as_uint(hnew)), "r"(dmbar) : "memory");
            }
        }
        if (lane == 8) {
            if (hs_out) hs_out[(size_t)t * H_DIM + j] = hnew;
            if (t == T_LEN - 1 && hT_out) hT_out[j] = hnew;
        }
    }

    // no st.async issued for the final step -> no in-flight traffic; sync & exit
    asm volatile("barrier.cluster.arrive.aligned;" ::: "memory");
    asm volatile("barrier.cluster.wait.aligned;"   ::: "memory");
}

// ---------------- launch --------------------------------------------------------
extern "C" void kernel_launch(void* const* d_in, const int* in_sizes, int n_in,
                              void* d_out, int out_size)
{
    const float* x      = (const float*)d_in[0];   // [1, T, I]
    const float* W_ih_e = (const float*)d_in[2];   // [768, 1739]
    const float* W_hh_e = (const float*)d_in[3];   // [768, 256]
    const float* b_ih_e = (const float*)d_in[4];   // [768]
    const float* b_hh_e = (const float*)d_in[5];   // [768]
    const float* W_ih_d = (const float*)d_in[6];
    const float* W_hh_d = (const float*)d_in[7];
    const float* b_ih_d = (const float*)d_in[8];
    const float* b_hh_d = (const float*)d_in[9];
    const float* W_out  = (const float*)d_in[10];  // [1739, 256]
    const float* b_out  = (const float*)d_in[11];  // [1739]
    float* out = (float*)d_out;                    // [2048, 1, 1739]

    float *xpe, *xpd, *hs, *henc;
    cudaGetSymbolAddress((void**)&xpe,  g_xproj_enc);
    cudaGetSymbolAddress((void**)&xpd,  g_xproj_dec);
    cudaGetSymbolAddress((void**)&hs,   g_hs);
    cudaGetSymbolAddress((void**)&henc, g_henc);

    const dim3 blk(256);
    // x-projections (independent)
    gemm_bias_kernel<<<dim3(G3 / BN, T_LEN / BM), blk>>>(x, W_ih_e, b_ih_e, xpe,
                                                         T_LEN, G3, I_DIM);
    gemm_bias_kernel<<<dim3(G3 / BN, T_LEN / BM), blk>>>(x, W_ih_d, b_ih_d, xpd,
                                                         T_LEN, G3, I_DIM);
    // encoder recurrence -> h_enc
    gru_kernel<<<NCTA, 1024>>>(xpe, W_hh_e, b_hh_e, nullptr, nullptr, henc);
    // decoder recurrence (h0 = h_enc) -> hs
    gru_kernel<<<NCTA, 1024>>>(xpd, W_hh_d, b_hh_d, henc, hs, nullptr);
    // output projection
    gemm_bias_kernel<<<dim3((I_DIM + BN - 1) / BN, T_LEN / BM), blk>>>(
        hs, W_out, b_out, out, T_LEN, I_DIM, H_DIM);
}